// round 5
// baseline (speedup 1.0000x reference)
#include <cuda_runtime.h>
#include <cstdint>
#include <cstddef>

#define NB 16
#define HH 256
#define WW 256
#define NPIX (NB * HH * WW)        // 1,048,576 pixels (per-channel BN count)
#define C1 128
#define C2 64

// ---------------- static device scratch (no allocations allowed) ----------------
__device__ uint32_t           g_xbits[NB * HH * (WW / 32)];   // packed sign(x), 128KB
__device__ unsigned long long g_wb1[C1];                      // 49-bit weight signs, layer1
__device__ uint4              g_wb2[C2];                      // 128-bit weight signs, layer2
__device__ unsigned           g_sd[C1];                       // sum d
__device__ unsigned           g_sdd[C1];                      // sum d^2
__device__ unsigned           g_sid[C1];                      // sum inb*d
__device__ int                g_lo[C1];                       // sign threshold interval lo
__device__ int                g_wd[C1];                       // interval width (hi-lo)
__device__ unsigned long long g_sk[C2];                       // sum k
__device__ unsigned long long g_qk[C2];                       // sum k^2
__device__ float              g_P[C2], g_Q[C2];               // h2 = lrelu(P*k + Q)
__device__ int                g_tile;                         // conv3 work-steal counter
__device__ unsigned char      g_k2[(size_t)NB * C2 * HH * WW];// 64MB layer2 popcounts

// ---------------- prep: pack weight signs + zero stats ----------------
__global__ void k_prep(const float* __restrict__ w1, const float* __restrict__ w2) {
    int t = threadIdx.x;
    if (t < C1) {
        unsigned long long b = 0ull;
        #pragma unroll
        for (int j = 0; j < 49; j++)
            if (w1[t * 49 + j] >= 0.f) b |= (1ull << j);
        g_wb1[t] = b;
        g_sd[t] = 0u; g_sdd[t] = 0u; g_sid[t] = 0u;
    }
    if (t < C2) {
        uint32_t w[4];
        #pragma unroll
        for (int q = 0; q < 4; q++) {
            uint32_t b = 0u;
            #pragma unroll
            for (int j = 0; j < 32; j++)
                if (w2[t * 128 + q * 32 + j] >= 0.f) b |= (1u << j);
            w[q] = b;
        }
        g_wb2[t] = make_uint4(w[0], w[1], w[2], w[3]);
        g_sk[t] = 0ull;
        g_qk[t] = 0ull;
    }
}

// ---------------- pack sign(x) into bitmap ----------------
__global__ void k_packx(const float* __restrict__ x) {
    int idx = blockIdx.x * 256 + threadIdx.x;
    unsigned b = __ballot_sync(0xFFFFFFFFu, x[idx] >= 0.f);
    if ((threadIdx.x & 31) == 0) g_xbits[idx >> 5] = b;
}

// ---------------- 7x7 window of sign bits + validity mask ----------------
__device__ __forceinline__ void build_window(int n, int y, int x,
                                             unsigned long long& win,
                                             unsigned long long& msk) {
    const uint32_t* rowbase = g_xbits + (n << 11);
    uint32_t colmask = 0x7Fu;
    if (x < 3)   colmask &= (0x7Fu << (3 - x));
    if (x > 252) colmask &= (0x7Fu >> (x - 252));
    colmask &= 0x7Fu;
    int base = x - 3;
    int wi = (base >= 0) ? (base >> 5) : -1;
    int sh = base & 31;
    win = 0ull; msk = 0ull;
    #pragma unroll
    for (int r = 0; r < 7; r++) {
        int yy = y + r - 3;
        if (yy >= 0 && yy < HH) {
            const uint32_t* rw = rowbase + (yy << 3);
            uint32_t w0 = (wi >= 0) ? rw[wi] : 0u;
            uint32_t w1 = (wi < 7) ? rw[wi + 1] : 0u;
            uint32_t bits = __funnelshift_r(w0, w1, sh) & colmask;
            win |= (unsigned long long)bits << (7 * r);
            msk |= (unsigned long long)colmask << (7 * r);
        }
    }
}

// ---------------- pass 1 (transposed): layer1 conv -> per-channel stats -----------
// thread = channel; pixels staged through smem; register accumulation, no REDUX,
// no per-pixel atomics. Sum(inb) and Sum(inb^2) are closed-form constants.
__global__ void k_stats1() {
    __shared__ ulonglong2 s_wm[128];   // (win, msk) per staged pixel
    __shared__ int        s_inb[128];
    int t = threadIdx.x;               // channel id, 0..127
    unsigned long long wb = g_wb1[t];
    unsigned sd = 0u, sdd = 0u, sid = 0u;
    int base = blockIdx.x * 4096;

    for (int stage = 0; stage < 32; stage++) {
        int p = base + stage * 128 + t;
        int n = p >> 16;
        int rem = p & 65535;
        int y = rem >> 8;
        int x = rem & 255;
        unsigned long long win, msk;
        build_window(n, y, x, win, msk);
        __syncthreads();               // previous stage fully consumed
        s_wm[t] = make_ulonglong2(win, msk);
        s_inb[t] = __popcll(msk);
        __syncthreads();

        #pragma unroll 8
        for (int i = 0; i < 128; i++) {
            ulonglong2 wm = s_wm[i];
            int d = __popcll((wm.x ^ wb) & wm.y);
            int inb = s_inb[i];
            sd  += (unsigned)d;
            sdd += (unsigned)(d * d);
            sid += (unsigned)(inb * d);
        }
    }
    atomicAdd(&g_sd[t], sd);
    atomicAdd(&g_sdd[t], sdd);
    atomicAdd(&g_sid[t], sid);
}

// ---------------- finalize BN1 -> integer sign-threshold interval on v ----------------
__global__ void k_fin1(const float* __restrict__ g1, const float* __restrict__ b1) {
    int c = threadIdx.x;
    if (c >= C1) return;
    const double N = (double)NPIX;
    // Sum inb   = 16 * 1780^2   = 50,694,400
    // Sum inb^2 = 16 * 12404^2  = 2,461,747,456   (data-independent border constants)
    double Sv = 50694400.0 - 2.0 * (double)g_sd[c];
    double Sq = 2461747456.0 - 4.0 * (double)g_sid[c] + 4.0 * (double)g_sdd[c];
    double mean = Sv / N;
    double var  = Sq / N - mean * mean;
    float meanf = (float)mean;
    float invf  = g1[c] * rsqrtf((float)var + 1e-5f);
    float beta  = b1[c];
    int lo = 100, hi = -100;
    bool any = false;
    for (int v = -49; v <= 49; v++) {
        float h = ((float)v - meanf) * invf + beta;
        if (h >= 0.f) { if (!any) { lo = v; any = true; } hi = v; }
    }
    if (!any) { g_lo[c] = 100; g_wd[c] = 0; }
    else      { g_lo[c] = lo;  g_wd[c] = hi - lo; }
}

// ---------------- pass 3: layer1 signs -> layer2 1x1 binary conv (store k) -----------
__global__ void k_sign_conv2() {
    __shared__ unsigned long long s_wb[C1];
    __shared__ int s_lo[C1];
    __shared__ int s_wd[C1];
    __shared__ uint4 s_w2[C2];
    int t = threadIdx.x;
    if (t < C1) { s_wb[t] = g_wb1[t]; s_lo[t] = g_lo[t]; s_wd[t] = g_wd[t]; }
    if (t < C2) s_w2[t] = g_wb2[t];
    __syncthreads();

    int p = blockIdx.x * 256 + t;
    int n = p >> 16;
    int rem = p & 65535;
    int y = rem >> 8;
    int x = rem & 255;
    unsigned long long win, msk;
    build_window(n, y, x, win, msk);
    int inb = __popcll(msk);

    uint32_t sw[4];
    #pragma unroll
    for (int w = 0; w < 4; w++) {
        uint32_t bits = 0u;
        #pragma unroll
        for (int j = 0; j < 32; j++) {
            int c = w * 32 + j;
            int dis = __popcll((win ^ s_wb[c]) & msk);
            int v = inb - 2 * dis;
            if ((unsigned)(v - s_lo[c]) <= (unsigned)s_wd[c]) bits |= (1u << j);
        }
        sw[w] = bits;
    }

    unsigned char* outb = g_k2 + ((size_t)n << 22) + rem;
    #pragma unroll 8
    for (int oc = 0; oc < C2; oc++) {
        uint4 wb = s_w2[oc];
        int k = __popc(sw[0] ^ wb.x) + __popc(sw[1] ^ wb.y) +
                __popc(sw[2] ^ wb.z) + __popc(sw[3] ^ wb.w);
        outb[(size_t)oc << 16] = (unsigned char)k;
    }
}

// ---------------- stats for BN2 from k bytes (dp4a) ----------------
__global__ void k_stats2() {
    int b = blockIdx.x;           // b = n*64 + c
    int c = b & 63;
    int t = threadIdx.x;
    const uint4* ptr = (const uint4*)(g_k2 + ((size_t)b << 16));
    unsigned s = 0u, s2 = 0u;
    #pragma unroll
    for (int i = 0; i < 16; i++) {
        uint4 v = ptr[t + i * 256];
        s  = __dp4a(v.x, 0x01010101u, s);  s2 = __dp4a(v.x, v.x, s2);
        s  = __dp4a(v.y, 0x01010101u, s);  s2 = __dp4a(v.y, v.y, s2);
        s  = __dp4a(v.z, 0x01010101u, s);  s2 = __dp4a(v.z, v.z, s2);
        s  = __dp4a(v.w, 0x01010101u, s);  s2 = __dp4a(v.w, v.w, s2);
    }
    s  = __reduce_add_sync(0xFFFFFFFFu, s);
    s2 = __reduce_add_sync(0xFFFFFFFFu, s2);
    __shared__ unsigned sh_s, sh_s2;
    if (t == 0) { sh_s = 0u; sh_s2 = 0u; }
    __syncthreads();
    if ((t & 31) == 0) { atomicAdd(&sh_s, s); atomicAdd(&sh_s2, s2); }
    __syncthreads();
    if (t == 0) {
        atomicAdd(&g_sk[c], (unsigned long long)sh_s);
        atomicAdd(&g_qk[c], (unsigned long long)sh_s2);
    }
}

// ---------------- finalize BN2 -> affine h2(k) = lrelu(P*k + Q); reset conv3 counter --
__global__ void k_fin2(const float* __restrict__ g2, const float* __restrict__ b2) {
    int c = threadIdx.x;
    if (c == 0) g_tile = 0;
    if (c >= C2) return;
    double N = (double)NPIX;
    double mk = (double)(long long)g_sk[c] / N;
    double qk = (double)g_qk[c] / N;
    double vark = qk - mk * mk;
    // v2 = 128 - 2k  ->  mean_v = 128 - 2*mk, var_v = 4*vark
    float meanv = (float)(128.0 - 2.0 * mk);
    float varv  = (float)(4.0 * vark);
    float inv   = g2[c] * rsqrtf(varv + 1e-5f);
    g_P[c] = -2.f * inv;
    g_Q[c] = (128.f - meanv) * inv + b2[c];
}

// ---------------- layer 3: fp32 5x5 conv, 64 ch -> 1 ch ----------------
// 64x32 tile, 4 rows x 4 cols per thread (8 rows preloaded in registers:
// 16 LDS.128 per 400 FFMA per channel). 4-channel smem groups. Persistent
// blocks with work-stealing over the 512 tiles (deterministic: tiles independent).
__global__ void __launch_bounds__(128, 3) k_conv3(const float* __restrict__ w3,
                                                  float* __restrict__ out) {
    __shared__ float ht[4][36][72];     // 41,472 B
    __shared__ float w3s[C2 * 25];      //  6,400 B
    __shared__ float Ps[C2], Qs[C2];    //    512 B
    __shared__ int   s_tile;
    int t  = threadIdx.x;               // 0..127
    int tx = t & 15;                    // 16 x-groups of 4 cols -> 64 cols
    int ty = t >> 4;                    // 8 y-groups of 4 rows  -> 32 rows
    for (int i = t; i < C2 * 25; i += 128) w3s[i] = w3[i];
    if (t < C2) { Ps[t] = g_P[t]; Qs[t] = g_Q[t]; }

    while (true) {
        if (t == 0) s_tile = atomicAdd(&g_tile, 1);
        __syncthreads();                // also covers w3s/Ps/Qs on first pass
        int idx = s_tile;
        if (idx >= 512) break;
        int n  = idx >> 5;
        int r  = idx & 31;
        int Y0 = (r >> 2) * 32;
        int X0 = (r & 3) * 64;
        const unsigned char* kb = g_k2 + ((size_t)n << 22);

        float acc[4][4];
        #pragma unroll
        for (int a = 0; a < 4; a++)
            #pragma unroll
            for (int bq = 0; bq < 4; bq++) acc[a][bq] = 0.f;

        for (int g = 0; g < 16; g++) {
            int c0 = g * 4;
            __syncthreads();            // previous group fully consumed
            // fill 36x68 halo tile for 4 channels, k -> lrelu(P*k+Q)
            for (int i = t; i < 36 * 68; i += 128) {
                int yy = i / 68;
                int xx = i - yy * 68;
                int gy = Y0 - 2 + yy;
                int gx = X0 - 2 + xx;
                bool ok = ((unsigned)gy < 256u) && ((unsigned)gx < 256u);
                int off = gy * 256 + gx;
                #pragma unroll
                for (int c = 0; c < 4; c++) {
                    float val = 0.f;
                    if (ok) {
                        float kk = (float)kb[((size_t)(c0 + c) << 16) + off];
                        float h = fmaf(Ps[c0 + c], kk, Qs[c0 + c]);
                        val = fmaxf(h, 0.5f * h);   // LeakyReLU(0.5)
                    }
                    ht[c][yy][xx] = val;
                }
            }
            __syncthreads();

            #pragma unroll
            for (int c = 0; c < 4; c++) {
                // preload 8 rows x 8 cols into registers
                float4 A[8], B[8];
                #pragma unroll
                for (int rr = 0; rr < 8; rr++) {
                    const float* rowp = &ht[c][ty * 4 + rr][tx * 4];
                    A[rr] = *(const float4*)rowp;
                    B[rr] = *(const float4*)(rowp + 4);
                }
                const float* wrow = &w3s[(c0 + c) * 25];
                #pragma unroll
                for (int ky = 0; ky < 5; ky++) {
                    float w0 = wrow[ky * 5 + 0];
                    float w1 = wrow[ky * 5 + 1];
                    float w2 = wrow[ky * 5 + 2];
                    float w3v = wrow[ky * 5 + 3];
                    float w4 = wrow[ky * 5 + 4];
                    #pragma unroll
                    for (int ry = 0; ry < 4; ry++) {
                        int rr = ry + ky;
                        float i0 = A[rr].x, i1 = A[rr].y, i2 = A[rr].z, i3 = A[rr].w;
                        float i4 = B[rr].x, i5 = B[rr].y, i6 = B[rr].z, i7 = B[rr].w;
                        acc[ry][0] = fmaf(i0, w0, fmaf(i1, w1, fmaf(i2, w2, fmaf(i3, w3v, fmaf(i4, w4, acc[ry][0])))));
                        acc[ry][1] = fmaf(i1, w0, fmaf(i2, w1, fmaf(i3, w2, fmaf(i4, w3v, fmaf(i5, w4, acc[ry][1])))));
                        acc[ry][2] = fmaf(i2, w0, fmaf(i3, w1, fmaf(i4, w2, fmaf(i5, w3v, fmaf(i6, w4, acc[ry][2])))));
                        acc[ry][3] = fmaf(i3, w0, fmaf(i4, w1, fmaf(i5, w2, fmaf(i6, w3v, fmaf(i7, w4, acc[ry][3])))));
                    }
                }
            }
        }

        #pragma unroll
        for (int ry = 0; ry < 4; ry++) {
            int yo = Y0 + ty * 4 + ry;
            float4 v = make_float4(acc[ry][0], acc[ry][1], acc[ry][2], acc[ry][3]);
            *(float4*)&out[(n << 16) + yo * 256 + X0 + tx * 4] = v;
        }
    }
}

// ---------------- launch ----------------
extern "C" void kernel_launch(void* const* d_in, const int* in_sizes, int n_in,
                              void* d_out, int out_size) {
    const float* x  = (const float*)d_in[0];
    const float* w1 = (const float*)d_in[1];
    const float* g1 = (const float*)d_in[2];
    const float* b1 = (const float*)d_in[3];
    const float* w2 = (const float*)d_in[4];
    const float* g2 = (const float*)d_in[5];
    const float* b2 = (const float*)d_in[6];
    const float* w3 = (const float*)d_in[7];
    float* out = (float*)d_out;

    k_prep<<<1, 256>>>(w1, w2);
    k_packx<<<NPIX / 256, 256>>>(x);
    k_stats1<<<NPIX / 4096, 128>>>();
    k_fin1<<<1, 128>>>(g1, b1);
    k_sign_conv2<<<NPIX / 256, 256>>>();
    k_stats2<<<NB * C2, 256>>>();
    k_fin2<<<1, 64>>>(g2, b2);
    k_conv3<<<444, 128>>>(w3, out);
    (void)in_sizes; (void)n_in; (void)out_size;
}

// round 6
// speedup vs baseline: 1.4819x; 1.4819x over previous
#include <cuda_runtime.h>
#include <cstdint>
#include <cstddef>

#define NB 16
#define HH 256
#define WW 256
#define NPIX (NB * HH * WW)        // 1,048,576 pixels (per-channel BN count)
#define C1 128
#define C2 64

// ---------------- static device scratch (no allocations allowed) ----------------
__device__ uint32_t           g_xbits[NB * HH * (WW / 32)];   // packed sign(x), 128KB
__device__ unsigned long long g_wb1[C1];                      // 49-bit weight signs, layer1
__device__ uint4              g_wb2[C2];                      // 128-bit weight signs, layer2
__device__ unsigned long long g_s1[C1];                       // sum v1 (2's complement)
__device__ unsigned long long g_q1[C1];                       // sum v1^2
__device__ int                g_lo[C1];                       // sign threshold interval lo
__device__ int                g_wd[C1];                       // interval width (hi-lo)
__device__ unsigned long long g_sk[C2];                       // sum k
__device__ unsigned long long g_qk[C2];                       // sum k^2
__device__ float              g_P[C2], g_Q[C2];               // h2 = lrelu(P*k + Q)
__device__ unsigned char      g_k2[(size_t)NB * C2 * HH * WW];// 64MB layer2 popcounts

// ---------------- prep: pack weight signs + zero stats ----------------
__global__ void k_prep(const float* __restrict__ w1, const float* __restrict__ w2) {
    int t = threadIdx.x;
    if (t < C1) {
        unsigned long long b = 0ull;
        #pragma unroll
        for (int j = 0; j < 49; j++)
            if (w1[t * 49 + j] >= 0.f) b |= (1ull << j);
        g_wb1[t] = b;
        g_s1[t] = 0ull;
        g_q1[t] = 0ull;
    }
    if (t < C2) {
        uint32_t w[4];
        #pragma unroll
        for (int q = 0; q < 4; q++) {
            uint32_t b = 0u;
            #pragma unroll
            for (int j = 0; j < 32; j++)
                if (w2[t * 128 + q * 32 + j] >= 0.f) b |= (1u << j);
            w[q] = b;
        }
        g_wb2[t] = make_uint4(w[0], w[1], w[2], w[3]);
        g_sk[t] = 0ull;
        g_qk[t] = 0ull;
    }
}

// ---------------- pack sign(x) into bitmap ----------------
__global__ void k_packx(const float* __restrict__ x) {
    int idx = blockIdx.x * 256 + threadIdx.x;
    unsigned b = __ballot_sync(0xFFFFFFFFu, x[idx] >= 0.f);
    if ((threadIdx.x & 31) == 0) g_xbits[idx >> 5] = b;
}

// ---------------- 7x7 window of sign bits + validity mask ----------------
__device__ __forceinline__ void build_window(int n, int y, int x,
                                             unsigned long long& win,
                                             unsigned long long& msk) {
    const uint32_t* rowbase = g_xbits + (n << 11);
    uint32_t colmask = 0x7Fu;
    if (x < 3)   colmask &= (0x7Fu << (3 - x));
    if (x > 252) colmask &= (0x7Fu >> (x - 252));
    colmask &= 0x7Fu;
    int base = x - 3;
    int wi = (base >= 0) ? (base >> 5) : -1;
    int sh = base & 31;
    win = 0ull; msk = 0ull;
    #pragma unroll
    for (int r = 0; r < 7; r++) {
        int yy = y + r - 3;
        if (yy >= 0 && yy < HH) {
            const uint32_t* rw = rowbase + (yy << 3);
            uint32_t w0 = (wi >= 0) ? rw[wi] : 0u;
            uint32_t w1 = (wi < 7) ? rw[wi + 1] : 0u;
            uint32_t bits = __funnelshift_r(w0, w1, sh) & colmask;
            win |= (unsigned long long)bits << (7 * r);
            msk |= (unsigned long long)colmask << (7 * r);
        }
    }
}

// ---------------- pass 1: layer1 conv -> per-channel integer stats ----------------
// 8-pixel batching: each thread builds 8 windows (registers), then per channel
// accumulates v and v^2 over the 8 pixels before one REDUX + one shared atomic.
// This cuts REDUX/ATOMS count 8x vs the 1-pixel version.
__global__ void k_conv1_stats() {
    __shared__ unsigned long long s_wb[C1];
    __shared__ int s_sum[C1];
    __shared__ int s_sq[C1];
    int t = threadIdx.x;
    if (t < C1) { s_wb[t] = g_wb1[t]; s_sum[t] = 0; s_sq[t] = 0; }
    __syncthreads();

    // 8 pixels per thread: p_k = blockIdx.x*2048 + k*256 + t (all in same image n)
    int base = blockIdx.x * 2048 + t;
    int n = base >> 16;
    unsigned long long win[8], msk[8];
    int inb[8];
    #pragma unroll
    for (int k = 0; k < 8; k++) {
        int p = base + k * 256;
        int rem = p & 65535;
        build_window(n, rem >> 8, rem & 255, win[k], msk[k]);
        inb[k] = __popcll(msk[k]);
    }
    int lane = t & 31;

    #pragma unroll 4
    for (int c = 0; c < C1; c++) {
        unsigned long long wb = s_wb[c];
        int s = 0, s2 = 0;
        #pragma unroll
        for (int k = 0; k < 8; k++) {
            int d = __popcll((win[k] ^ wb) & msk[k]);
            int v = inb[k] - 2 * d;
            s += v;
            s2 += v * v;
        }
        s  = __reduce_add_sync(0xFFFFFFFFu, s);
        s2 = __reduce_add_sync(0xFFFFFFFFu, s2);
        if (lane == 0) { atomicAdd(&s_sum[c], s); atomicAdd(&s_sq[c], s2); }
    }
    __syncthreads();
    if (t < C1) {
        atomicAdd(&g_s1[t], (unsigned long long)(long long)s_sum[t]);
        atomicAdd(&g_q1[t], (unsigned long long)(long long)s_sq[t]);
    }
}

// ---------------- finalize BN1 -> integer sign-threshold interval on v ----------------
__global__ void k_fin1(const float* __restrict__ g1, const float* __restrict__ b1) {
    int c = threadIdx.x;
    if (c >= C1) return;
    double N = (double)NPIX;
    double S1 = (double)(long long)g_s1[c];
    double S2 = (double)g_q1[c];
    double mean = S1 / N;
    double var  = S2 / N - mean * mean;
    float meanf = (float)mean;
    float invf  = g1[c] * rsqrtf((float)var + 1e-5f);
    float beta  = b1[c];
    int lo = 100, hi = -100;
    bool any = false;
    for (int v = -49; v <= 49; v++) {
        float h = ((float)v - meanf) * invf + beta;
        if (h >= 0.f) { if (!any) { lo = v; any = true; } hi = v; }
    }
    if (!any) { g_lo[c] = 100; g_wd[c] = 0; }
    else      { g_lo[c] = lo;  g_wd[c] = hi - lo; }
}

// ---------------- pass 3: layer1 signs -> layer2 1x1 binary conv (store k) -----------
__global__ void k_sign_conv2() {
    __shared__ unsigned long long s_wb[C1];
    __shared__ int s_lo[C1];
    __shared__ int s_wd[C1];
    __shared__ uint4 s_w2[C2];
    int t = threadIdx.x;
    if (t < C1) { s_wb[t] = g_wb1[t]; s_lo[t] = g_lo[t]; s_wd[t] = g_wd[t]; }
    if (t < C2) s_w2[t] = g_wb2[t];
    __syncthreads();

    int p = blockIdx.x * 256 + t;
    int n = p >> 16;
    int rem = p & 65535;
    int y = rem >> 8;
    int x = rem & 255;
    unsigned long long win, msk;
    build_window(n, y, x, win, msk);
    int inb = __popcll(msk);

    uint32_t sw[4];
    #pragma unroll
    for (int w = 0; w < 4; w++) {
        uint32_t bits = 0u;
        #pragma unroll
        for (int j = 0; j < 32; j++) {
            int c = w * 32 + j;
            int dis = __popcll((win ^ s_wb[c]) & msk);
            int v = inb - 2 * dis;
            if ((unsigned)(v - s_lo[c]) <= (unsigned)s_wd[c]) bits |= (1u << j);
        }
        sw[w] = bits;
    }

    unsigned char* outb = g_k2 + ((size_t)n << 22) + rem;
    #pragma unroll 8
    for (int oc = 0; oc < C2; oc++) {
        uint4 wb = s_w2[oc];
        int k = __popc(sw[0] ^ wb.x) + __popc(sw[1] ^ wb.y) +
                __popc(sw[2] ^ wb.z) + __popc(sw[3] ^ wb.w);
        outb[(size_t)oc << 16] = (unsigned char)k;
    }
}

// ---------------- stats for BN2 from k bytes (dp4a) ----------------
__global__ void k_stats2() {
    int b = blockIdx.x;           // b = n*64 + c
    int c = b & 63;
    int t = threadIdx.x;
    const uint4* ptr = (const uint4*)(g_k2 + ((size_t)b << 16));
    unsigned s = 0u, s2 = 0u;
    #pragma unroll
    for (int i = 0; i < 16; i++) {
        uint4 v = ptr[t + i * 256];
        s  = __dp4a(v.x, 0x01010101u, s);  s2 = __dp4a(v.x, v.x, s2);
        s  = __dp4a(v.y, 0x01010101u, s);  s2 = __dp4a(v.y, v.y, s2);
        s  = __dp4a(v.z, 0x01010101u, s);  s2 = __dp4a(v.z, v.z, s2);
        s  = __dp4a(v.w, 0x01010101u, s);  s2 = __dp4a(v.w, v.w, s2);
    }
    s  = __reduce_add_sync(0xFFFFFFFFu, s);
    s2 = __reduce_add_sync(0xFFFFFFFFu, s2);
    __shared__ unsigned sh_s, sh_s2;
    if (t == 0) { sh_s = 0u; sh_s2 = 0u; }
    __syncthreads();
    if ((t & 31) == 0) { atomicAdd(&sh_s, s); atomicAdd(&sh_s2, s2); }
    __syncthreads();
    if (t == 0) {
        atomicAdd(&g_sk[c], (unsigned long long)sh_s);
        atomicAdd(&g_qk[c], (unsigned long long)sh_s2);
    }
}

// ---------------- finalize BN2 -> affine h2(k) = lrelu(P*k + Q) ----------------
__global__ void k_fin2(const float* __restrict__ g2, const float* __restrict__ b2) {
    int c = threadIdx.x;
    if (c >= C2) return;
    double N = (double)NPIX;
    double mk = (double)(long long)g_sk[c] / N;
    double qk = (double)g_qk[c] / N;
    double vark = qk - mk * mk;
    // v2 = 128 - 2k  ->  mean_v = 128 - 2*mk, var_v = 4*vark
    float meanv = (float)(128.0 - 2.0 * mk);
    float varv  = (float)(4.0 * vark);
    float inv   = g2[c] * rsqrtf(varv + 1e-5f);
    g_P[c] = -2.f * inv;
    g_Q[c] = (128.f - meanv) * inv + b2[c];
}

// ---------------- layer 3: fp32 5x5 conv, 64 ch -> 1 ch, smem-tiled ----------------
// R3 grid/tile structure (32x32 tile, 8-channel smem groups, 1024 blocks), but:
//  - each thread outputs 2 CONTIGUOUS rows x 4 cols -> 6-row x 8-col register
//    preload: 12 LDS.128 per 200 FFMA per channel (vs 20 in R3)
//  - warp mapping tx=t>>4, ty=t&15: quarter-warps stride rows (8-bank stride,
//    2-way conflicts) instead of columns (4-way)
__global__ void k_conv3(const float* __restrict__ w3, float* __restrict__ out) {
    __shared__ float ht[8][36][36];     // 41,472 B
    __shared__ float w3s[C2 * 25];      //  6,400 B
    __shared__ float Ps[C2], Qs[C2];    //    512 B
    int t  = threadIdx.x;               // 0..127
    int tx = t >> 4;                    // 0..7  : cols 4*tx
    int ty = t & 15;                    // 0..15 : rows 2*ty
    for (int i = t; i < C2 * 25; i += 128) w3s[i] = w3[i];
    if (t < C2) { Ps[t] = g_P[t]; Qs[t] = g_Q[t]; }

    int n = blockIdx.z;
    int X0 = blockIdx.x * 32;
    int Y0 = blockIdx.y * 32;
    const unsigned char* kbase = g_k2 + ((size_t)n << 22);

    float acc[2][4] = {{0.f, 0.f, 0.f, 0.f}, {0.f, 0.f, 0.f, 0.f}};

    for (int g = 0; g < 8; g++) {
        int c0 = g * 8;
        __syncthreads();
        // load 36x36 tile (with halo) for 8 channels, convert k -> lrelu(P*k+Q)
        for (int i = t; i < 1296; i += 128) {
            int yy = i / 36;
            int xx = i - yy * 36;
            int gy = Y0 - 2 + yy;
            int gx = X0 - 2 + xx;
            bool ok = ((unsigned)gy < 256u) && ((unsigned)gx < 256u);
            int off = gy * 256 + gx;
            #pragma unroll
            for (int c = 0; c < 8; c++) {
                float val = 0.f;
                if (ok) {
                    float kk = (float)kbase[((size_t)(c0 + c) << 16) + off];
                    float h = fmaf(Ps[c0 + c], kk, Qs[c0 + c]);
                    val = fmaxf(h, 0.5f * h);   // LeakyReLU(0.5)
                }
                ht[c][yy][xx] = val;
            }
        }
        __syncthreads();

        #pragma unroll
        for (int c = 0; c < 8; c++) {
            // preload 6 rows x 8 cols into registers
            float4 A[6], Bv[6];
            #pragma unroll
            for (int rr = 0; rr < 6; rr++) {
                const float* rowp = &ht[c][ty * 2 + rr][tx * 4];
                A[rr]  = *(const float4*)rowp;
                Bv[rr] = *(const float4*)(rowp + 4);
            }
            const float* wrow = &w3s[(c0 + c) * 25];
            #pragma unroll
            for (int ky = 0; ky < 5; ky++) {
                float w0 = wrow[ky * 5 + 0];
                float w1 = wrow[ky * 5 + 1];
                float w2 = wrow[ky * 5 + 2];
                float w3v = wrow[ky * 5 + 3];
                float w4 = wrow[ky * 5 + 4];
                #pragma unroll
                for (int ry = 0; ry < 2; ry++) {
                    int rr = ry + ky;       // 0..5
                    float i0 = A[rr].x, i1 = A[rr].y, i2 = A[rr].z, i3 = A[rr].w;
                    float i4 = Bv[rr].x, i5 = Bv[rr].y, i6 = Bv[rr].z, i7 = Bv[rr].w;
                    acc[ry][0] = fmaf(i0, w0, fmaf(i1, w1, fmaf(i2, w2, fmaf(i3, w3v, fmaf(i4, w4, acc[ry][0])))));
                    acc[ry][1] = fmaf(i1, w0, fmaf(i2, w1, fmaf(i3, w2, fmaf(i4, w3v, fmaf(i5, w4, acc[ry][1])))));
                    acc[ry][2] = fmaf(i2, w0, fmaf(i3, w1, fmaf(i4, w2, fmaf(i5, w3v, fmaf(i6, w4, acc[ry][2])))));
                    acc[ry][3] = fmaf(i3, w0, fmaf(i4, w1, fmaf(i5, w2, fmaf(i6, w3v, fmaf(i7, w4, acc[ry][3])))));
                }
            }
        }
    }

    #pragma unroll
    for (int ry = 0; ry < 2; ry++) {
        int yo = Y0 + ty * 2 + ry;
        float4 v = make_float4(acc[ry][0], acc[ry][1], acc[ry][2], acc[ry][3]);
        *(float4*)&out[(n << 16) + yo * 256 + X0 + tx * 4] = v;
    }
}

// ---------------- launch ----------------
extern "C" void kernel_launch(void* const* d_in, const int* in_sizes, int n_in,
                              void* d_out, int out_size) {
    const float* x  = (const float*)d_in[0];
    const float* w1 = (const float*)d_in[1];
    const float* g1 = (const float*)d_in[2];
    const float* b1 = (const float*)d_in[3];
    const float* w2 = (const float*)d_in[4];
    const float* g2 = (const float*)d_in[5];
    const float* b2 = (const float*)d_in[6];
    const float* w3 = (const float*)d_in[7];
    float* out = (float*)d_out;

    k_prep<<<1, 256>>>(w1, w2);
    k_packx<<<NPIX / 256, 256>>>(x);
    k_conv1_stats<<<NPIX / 2048, 256>>>();
    k_fin1<<<1, 128>>>(g1, b1);
    k_sign_conv2<<<NPIX / 256, 256>>>();
    k_stats2<<<NB * C2, 256>>>();
    k_fin2<<<1, 64>>>(g2, b2);
    k_conv3<<<dim3(8, 8, NB), dim3(128)>>>(w3, out);
    (void)in_sizes; (void)n_in; (void)out_size;
}

// round 7
// speedup vs baseline: 1.6253x; 1.0968x over previous
#include <cuda_runtime.h>
#include <cstdint>
#include <cstddef>

#define NB 16
#define HH 256
#define WW 256
#define NPIX (NB * HH * WW)        // 1,048,576 pixels (per-channel BN count)
#define C1 128
#define C2 64

// ---------------- static device scratch (no allocations allowed) ----------------
__device__ uint32_t           g_xbits[NB * HH * (WW / 32)];   // packed sign(x), 128KB
__device__ unsigned long long g_wb1[C1];                      // 49-bit weight signs, layer1
__device__ uint4              g_wb2[C2];                      // 128-bit weight signs, layer2
__device__ unsigned long long g_s1[C1];                       // sum v1 (2's complement)
__device__ unsigned long long g_q1[C1];                       // sum v1^2
__device__ int                g_lo[C1];                       // v-interval lo (border path)
__device__ int                g_wd[C1];                       // v-interval width
__device__ int                g_ilo[C1];                      // d-interval lo (interior path)
__device__ int                g_iwd[C1];                      // d-interval width
__device__ unsigned long long g_sk[C2];                       // sum k
__device__ unsigned long long g_qk[C2];                       // sum k^2
__device__ float              g_P[C2], g_Q[C2];               // h2 = lrelu(P*k + Q)
__device__ unsigned char      g_k2[(size_t)NB * C2 * HH * WW];// 64MB layer2 popcounts

// ---------------- pack sign(x) into bitmap; block 0 also packs weights + zeroes stats
__global__ void k_packx(const float* __restrict__ x,
                        const float* __restrict__ w1,
                        const float* __restrict__ w2) {
    int t = threadIdx.x;
    if (blockIdx.x == 0) {
        if (t < C1) {
            unsigned long long b = 0ull;
            #pragma unroll
            for (int j = 0; j < 49; j++)
                if (w1[t * 49 + j] >= 0.f) b |= (1ull << j);
            g_wb1[t] = b;
            g_s1[t] = 0ull;
            g_q1[t] = 0ull;
        }
        if (t < C2) {
            uint32_t w[4];
            #pragma unroll
            for (int q = 0; q < 4; q++) {
                uint32_t b = 0u;
                #pragma unroll
                for (int j = 0; j < 32; j++)
                    if (w2[t * 128 + q * 32 + j] >= 0.f) b |= (1u << j);
                w[q] = b;
            }
            g_wb2[t] = make_uint4(w[0], w[1], w[2], w[3]);
            g_sk[t] = 0ull;
            g_qk[t] = 0ull;
        }
    }
    int idx = blockIdx.x * 256 + t;
    unsigned b = __ballot_sync(0xFFFFFFFFu, x[idx] >= 0.f);
    if ((t & 31) == 0) g_xbits[idx >> 5] = b;
}

// ---------------- 7x7 window of sign bits + validity mask (border-safe) -------------
__device__ __forceinline__ void build_window(int n, int y, int x,
                                             unsigned long long& win,
                                             unsigned long long& msk) {
    const uint32_t* rowbase = g_xbits + (n << 11);
    uint32_t colmask = 0x7Fu;
    if (x < 3)   colmask &= (0x7Fu << (3 - x));
    if (x > 252) colmask &= (0x7Fu >> (x - 252));
    colmask &= 0x7Fu;
    int base = x - 3;
    int wi = (base >= 0) ? (base >> 5) : -1;
    int sh = base & 31;
    win = 0ull; msk = 0ull;
    #pragma unroll
    for (int r = 0; r < 7; r++) {
        int yy = y + r - 3;
        if (yy >= 0 && yy < HH) {
            const uint32_t* rw = rowbase + (yy << 3);
            uint32_t w0 = (wi >= 0) ? rw[wi] : 0u;
            uint32_t w1 = (wi < 7) ? rw[wi + 1] : 0u;
            uint32_t bits = __funnelshift_r(w0, w1, sh) & colmask;
            win |= (unsigned long long)bits << (7 * r);
            msk |= (unsigned long long)colmask << (7 * r);
        }
    }
}

// ---------------- unguarded interior window from shared row bits --------------------
__device__ __forceinline__ unsigned long long win_from_rows(const uint32_t* rb) {
    unsigned long long w = 0ull;
    #pragma unroll
    for (int r = 0; r < 7; r++)
        w |= (unsigned long long)rb[r] << (7 * r);
    return w;
}

// ---------------- pass 1: layer1 conv -> per-channel integer stats ----------------
// 8 pixels per thread (8 consecutive rows, same x). Interior warps take a fast
// path: 14 shared row-fetches build all 8 windows; no masks; accumulate only
// (sum d, sum d^2) per channel and convert to (sum v, sum v^2) once per REDUX.
__global__ void k_conv1_stats() {
    __shared__ unsigned long long s_wb[C1];
    __shared__ int s_sum[C1];
    __shared__ int s_sq[C1];
    int t = threadIdx.x;
    if (t < C1) { s_wb[t] = g_wb1[t]; s_sum[t] = 0; s_sq[t] = 0; }
    __syncthreads();

    int base = blockIdx.x * 2048 + t;
    int n  = base >> 16;
    int r0 = (blockIdx.x * 8) & 255;     // first of 8 rows this block covers
    int x  = t;                          // column (block spans full rows)
    int lane = t & 31;
    int xw = t & 224;                    // warp x-start (multiple of 32)
    bool wint = (xw != 0) && (xw != 224) && (r0 >= 8) && (r0 <= 240);

    if (wint) {
        // ---- interior fast path ----
        const uint32_t* rowbase = g_xbits + (n << 11);
        int bm3 = x - 3;                 // x in [32,223] -> wi in [0,6]
        int wi = bm3 >> 5;
        int sh = bm3 & 31;
        uint32_t rb[14];
        #pragma unroll
        for (int j = 0; j < 14; j++) {
            const uint32_t* rw = rowbase + ((r0 - 3 + j) << 3);
            rb[j] = __funnelshift_r(rw[wi], rw[wi + 1], sh) & 0x7Fu;
        }
        unsigned long long win[8];
        #pragma unroll
        for (int k = 0; k < 8; k++) win[k] = win_from_rows(rb + k);

        #pragma unroll 4
        for (int c = 0; c < C1; c++) {
            unsigned long long wb = s_wb[c];
            int sd = 0, sdd = 0;
            #pragma unroll
            for (int k = 0; k < 8; k++) {
                int d = __popcll(win[k] ^ wb);
                sd += d;
                sdd += d * d;
            }
            int Sd  = __reduce_add_sync(0xFFFFFFFFu, sd);
            int Sdd = __reduce_add_sync(0xFFFFFFFFu, sdd);
            if (lane == 0) {
                // 256 px/warp: sum v = 256*49 - 2*Sd ; sum v^2 = 256*2401 - 196*Sd + 4*Sdd
                atomicAdd(&s_sum[c], 12544 - 2 * Sd);
                atomicAdd(&s_sq[c], 614656 - 196 * Sd + 4 * Sdd);
            }
        }
    } else {
        // ---- border path (exact masks) ----
        unsigned long long win[8], msk[8];
        int inb[8];
        #pragma unroll
        for (int k = 0; k < 8; k++) {
            int p = base + k * 256;
            int rem = p & 65535;
            build_window(n, rem >> 8, rem & 255, win[k], msk[k]);
            inb[k] = __popcll(msk[k]);
        }
        #pragma unroll 4
        for (int c = 0; c < C1; c++) {
            unsigned long long wb = s_wb[c];
            int s = 0, s2 = 0;
            #pragma unroll
            for (int k = 0; k < 8; k++) {
                int d = __popcll((win[k] ^ wb) & msk[k]);
                int v = inb[k] - 2 * d;
                s += v;
                s2 += v * v;
            }
            s  = __reduce_add_sync(0xFFFFFFFFu, s);
            s2 = __reduce_add_sync(0xFFFFFFFFu, s2);
            if (lane == 0) { atomicAdd(&s_sum[c], s); atomicAdd(&s_sq[c], s2); }
        }
    }
    __syncthreads();
    if (t < C1) {
        atomicAdd(&g_s1[t], (unsigned long long)(long long)s_sum[t]);
        atomicAdd(&g_q1[t], (unsigned long long)(long long)s_sq[t]);
    }
}

// ---------------- finalize BN1 -> sign-threshold intervals (v and d domains) --------
__global__ void k_fin1(const float* __restrict__ g1, const float* __restrict__ b1) {
    int c = threadIdx.x;
    if (c >= C1) return;
    double N = (double)NPIX;
    double S1 = (double)(long long)g_s1[c];
    double S2 = (double)g_q1[c];
    double mean = S1 / N;
    double var  = S2 / N - mean * mean;
    float meanf = (float)mean;
    float invf  = g1[c] * rsqrtf((float)var + 1e-5f);
    float beta  = b1[c];
    int lo = 100, hi = -100;
    bool any = false;
    for (int v = -49; v <= 49; v++) {
        float h = ((float)v - meanf) * invf + beta;
        if (h >= 0.f) { if (!any) { lo = v; any = true; } hi = v; }
    }
    int ilo = 100, iwd = 0;                 // d-interval for interior (v = 49-2d)
    if (!any) { g_lo[c] = 100; g_wd[c] = 0; }
    else {
        g_lo[c] = lo;  g_wd[c] = hi - lo;
        int dlo = (49 - hi + 1) >> 1;       // ceil((49-hi)/2)
        int dhi = (49 - lo) >> 1;           // floor((49-lo)/2)
        if (dlo < 0) dlo = 0;
        if (dhi > 49) dhi = 49;
        if (dhi >= dlo) { ilo = dlo; iwd = dhi - dlo; }
    }
    g_ilo[c] = ilo; g_iwd[c] = iwd;
}

// ---------------- pass 3: layer1 signs -> layer2 1x1 binary conv (store k) -----------
__global__ void k_sign_conv2() {
    __shared__ unsigned long long s_wb[C1];
    __shared__ int2 s_vi[C1];          // (lo, wd)  border
    __shared__ int2 s_di[C1];          // (ilo, iwd) interior
    __shared__ uint4 s_w2[C2];
    int t = threadIdx.x;
    if (t < C1) {
        s_wb[t] = g_wb1[t];
        s_vi[t] = make_int2(g_lo[t], g_wd[t]);
        s_di[t] = make_int2(g_ilo[t], g_iwd[t]);
    }
    if (t < C2) s_w2[t] = g_wb2[t];
    __syncthreads();

    int p = blockIdx.x * 256 + t;
    int n = p >> 16;
    int rem = p & 65535;
    int y = rem >> 8;                  // block-uniform (one row per block)
    int x = t;
    int xw = t & 224;
    bool wint = (xw != 0) && (xw != 224) && (y >= 3) && (y <= 252);

    uint32_t sw[4];
    if (wint) {
        // interior: unguarded window, threshold directly on d
        const uint32_t* rowbase = g_xbits + (n << 11);
        int bm3 = x - 3;
        int wi = bm3 >> 5;
        int sh = bm3 & 31;
        unsigned long long win = 0ull;
        #pragma unroll
        for (int r = 0; r < 7; r++) {
            const uint32_t* rw = rowbase + ((y + r - 3) << 3);
            uint32_t bits = __funnelshift_r(rw[wi], rw[wi + 1], sh) & 0x7Fu;
            win |= (unsigned long long)bits << (7 * r);
        }
        #pragma unroll
        for (int w = 0; w < 4; w++) {
            uint32_t bits = 0u;
            #pragma unroll
            for (int j = 0; j < 32; j++) {
                int c = w * 32 + j;
                int d = __popcll(win ^ s_wb[c]);
                int2 di = s_di[c];
                if ((unsigned)(d - di.x) <= (unsigned)di.y) bits |= (1u << j);
            }
            sw[w] = bits;
        }
    } else {
        unsigned long long win, msk;
        build_window(n, y, x, win, msk);
        int inb = __popcll(msk);
        #pragma unroll
        for (int w = 0; w < 4; w++) {
            uint32_t bits = 0u;
            #pragma unroll
            for (int j = 0; j < 32; j++) {
                int c = w * 32 + j;
                int dis = __popcll((win ^ s_wb[c]) & msk);
                int v = inb - 2 * dis;
                int2 vi = s_vi[c];
                if ((unsigned)(v - vi.x) <= (unsigned)vi.y) bits |= (1u << j);
            }
            sw[w] = bits;
        }
    }

    unsigned char* outb = g_k2 + ((size_t)n << 22) + rem;
    #pragma unroll 8
    for (int oc = 0; oc < C2; oc++) {
        uint4 wb = s_w2[oc];
        int k = __popc(sw[0] ^ wb.x) + __popc(sw[1] ^ wb.y) +
                __popc(sw[2] ^ wb.z) + __popc(sw[3] ^ wb.w);
        outb[(size_t)oc << 16] = (unsigned char)k;
    }
}

// ---------------- stats for BN2 from k bytes (dp4a) ----------------
__global__ void k_stats2() {
    int b = blockIdx.x;           // b = n*64 + c
    int c = b & 63;
    int t = threadIdx.x;
    const uint4* ptr = (const uint4*)(g_k2 + ((size_t)b << 16));
    unsigned s = 0u, s2 = 0u;
    #pragma unroll
    for (int i = 0; i < 16; i++) {
        uint4 v = ptr[t + i * 256];
        s  = __dp4a(v.x, 0x01010101u, s);  s2 = __dp4a(v.x, v.x, s2);
        s  = __dp4a(v.y, 0x01010101u, s);  s2 = __dp4a(v.y, v.y, s2);
        s  = __dp4a(v.z, 0x01010101u, s);  s2 = __dp4a(v.z, v.z, s2);
        s  = __dp4a(v.w, 0x01010101u, s);  s2 = __dp4a(v.w, v.w, s2);
    }
    s  = __reduce_add_sync(0xFFFFFFFFu, s);
    s2 = __reduce_add_sync(0xFFFFFFFFu, s2);
    __shared__ unsigned sh_s, sh_s2;
    if (t == 0) { sh_s = 0u; sh_s2 = 0u; }
    __syncthreads();
    if ((t & 31) == 0) { atomicAdd(&sh_s, s); atomicAdd(&sh_s2, s2); }
    __syncthreads();
    if (t == 0) {
        atomicAdd(&g_sk[c], (unsigned long long)sh_s);
        atomicAdd(&g_qk[c], (unsigned long long)sh_s2);
    }
}

// ---------------- finalize BN2 -> affine h2(k) = lrelu(P*k + Q) ----------------
__global__ void k_fin2(const float* __restrict__ g2, const float* __restrict__ b2) {
    int c = threadIdx.x;
    if (c >= C2) return;
    double N = (double)NPIX;
    double mk = (double)(long long)g_sk[c] / N;
    double qk = (double)g_qk[c] / N;
    double vark = qk - mk * mk;
    float meanv = (float)(128.0 - 2.0 * mk);
    float varv  = (float)(4.0 * vark);
    float inv   = g2[c] * rsqrtf(varv + 1e-5f);
    g_P[c] = -2.f * inv;
    g_Q[c] = (128.f - meanv) * inv + b2[c];
}

// ---------------- layer 3: fp32 5x5 conv, 64 ch -> 1 ch, smem-tiled ----------------
// 32x32 tile, 8-channel smem groups. Lane mapping tx=t&7, ty=t>>3: every 8-lane
// LDS.128 phase reads one contiguous 128B row -> conflict-free crossbar.
// 6-row x 8-col register preload: 12 LDS.128 per 200 FFMA per channel.
__global__ void k_conv3(const float* __restrict__ w3, float* __restrict__ out) {
    __shared__ float ht[8][36][36];     // 41,472 B
    __shared__ float w3s[C2 * 25];      //  6,400 B
    __shared__ float Ps[C2], Qs[C2];    //    512 B
    int t  = threadIdx.x;               // 0..127
    int tx = t & 7;                     // 0..7  : cols 4*tx
    int ty = t >> 3;                    // 0..15 : rows 2*ty
    for (int i = t; i < C2 * 25; i += 128) w3s[i] = w3[i];
    if (t < C2) { Ps[t] = g_P[t]; Qs[t] = g_Q[t]; }

    int n = blockIdx.z;
    int X0 = blockIdx.x * 32;
    int Y0 = blockIdx.y * 32;
    const unsigned char* kbase = g_k2 + ((size_t)n << 22);

    float acc[2][4] = {{0.f, 0.f, 0.f, 0.f}, {0.f, 0.f, 0.f, 0.f}};

    for (int g = 0; g < 8; g++) {
        int c0 = g * 8;
        __syncthreads();
        for (int i = t; i < 1296; i += 128) {
            int yy = i / 36;
            int xx = i - yy * 36;
            int gy = Y0 - 2 + yy;
            int gx = X0 - 2 + xx;
            bool ok = ((unsigned)gy < 256u) && ((unsigned)gx < 256u);
            int off = gy * 256 + gx;
            #pragma unroll
            for (int c = 0; c < 8; c++) {
                float val = 0.f;
                if (ok) {
                    float kk = (float)kbase[((size_t)(c0 + c) << 16) + off];
                    float h = fmaf(Ps[c0 + c], kk, Qs[c0 + c]);
                    val = fmaxf(h, 0.5f * h);   // LeakyReLU(0.5)
                }
                ht[c][yy][xx] = val;
            }
        }
        __syncthreads();

        #pragma unroll
        for (int c = 0; c < 8; c++) {
            float4 A[6], Bv[6];
            #pragma unroll
            for (int rr = 0; rr < 6; rr++) {
                const float* rowp = &ht[c][ty * 2 + rr][tx * 4];
                A[rr]  = *(const float4*)rowp;
                Bv[rr] = *(const float4*)(rowp + 4);
            }
            const float* wrow = &w3s[(c0 + c) * 25];
            #pragma unroll
            for (int ky = 0; ky < 5; ky++) {
                float w0 = wrow[ky * 5 + 0];
                float w1 = wrow[ky * 5 + 1];
                float w2 = wrow[ky * 5 + 2];
                float w3v = wrow[ky * 5 + 3];
                float w4 = wrow[ky * 5 + 4];
                #pragma unroll
                for (int ry = 0; ry < 2; ry++) {
                    int rr = ry + ky;
                    float i0 = A[rr].x, i1 = A[rr].y, i2 = A[rr].z, i3 = A[rr].w;
                    float i4 = Bv[rr].x, i5 = Bv[rr].y, i6 = Bv[rr].z, i7 = Bv[rr].w;
                    acc[ry][0] = fmaf(i0, w0, fmaf(i1, w1, fmaf(i2, w2, fmaf(i3, w3v, fmaf(i4, w4, acc[ry][0])))));
                    acc[ry][1] = fmaf(i1, w0, fmaf(i2, w1, fmaf(i3, w2, fmaf(i4, w3v, fmaf(i5, w4, acc[ry][1])))));
                    acc[ry][2] = fmaf(i2, w0, fmaf(i3, w1, fmaf(i4, w2, fmaf(i5, w3v, fmaf(i6, w4, acc[ry][2])))));
                    acc[ry][3] = fmaf(i3, w0, fmaf(i4, w1, fmaf(i5, w2, fmaf(i6, w3v, fmaf(i7, w4, acc[ry][3])))));
                }
            }
        }
    }

    #pragma unroll
    for (int ry = 0; ry < 2; ry++) {
        int yo = Y0 + ty * 2 + ry;
        float4 v = make_float4(acc[ry][0], acc[ry][1], acc[ry][2], acc[ry][3]);
        *(float4*)&out[(n << 16) + yo * 256 + X0 + tx * 4] = v;
    }
}

// ---------------- launch ----------------
extern "C" void kernel_launch(void* const* d_in, const int* in_sizes, int n_in,
                              void* d_out, int out_size) {
    const float* x  = (const float*)d_in[0];
    const float* w1 = (const float*)d_in[1];
    const float* g1 = (const float*)d_in[2];
    const float* b1 = (const float*)d_in[3];
    const float* w2 = (const float*)d_in[4];
    const float* g2 = (const float*)d_in[5];
    const float* b2 = (const float*)d_in[6];
    const float* w3 = (const float*)d_in[7];
    float* out = (float*)d_out;

    k_packx<<<NPIX / 256, 256>>>(x, w1, w2);
    k_conv1_stats<<<NPIX / 2048, 256>>>();
    k_fin1<<<1, 128>>>(g1, b1);
    k_sign_conv2<<<NPIX / 256, 256>>>();
    k_stats2<<<NB * C2, 256>>>();
    k_fin2<<<1, 64>>>(g2, b2);
    k_conv3<<<dim3(8, 8, NB), dim3(128)>>>(w3, out);
    (void)in_sizes; (void)n_in; (void)out_size;
}

// round 8
// speedup vs baseline: 1.6829x; 1.0355x over previous
#include <cuda_runtime.h>
#include <cstdint>
#include <cstddef>

#define NB 16
#define HH 256
#define WW 256
#define NPIX (NB * HH * WW)        // 1,048,576 pixels (per-channel BN count)
#define C1 128
#define C2 64

// ---------------- static device scratch (no allocations allowed) ----------------
__device__ uint32_t           g_xbits[NB * HH * (WW / 32)];   // packed sign(x), 128KB
__device__ unsigned long long g_wb1[C1];                      // 49-bit weight signs, layer1
__device__ uint4              g_wb2[C2];                      // 128-bit weight signs, layer2
__device__ unsigned long long g_s1[C1];                       // sum v1 (2's complement)
__device__ unsigned long long g_q1[C1];                       // sum v1^2
__device__ int                g_lo[C1];                       // v-interval lo (border path)
__device__ int                g_wd[C1];                       // v-interval width
__device__ int                g_ilo[C1];                      // d-interval lo (interior path)
__device__ int                g_iwd[C1];                      // d-interval width
__device__ unsigned long long g_sk[C2];                       // sum k
__device__ unsigned long long g_qk[C2];                       // sum k^2
__device__ float              g_P[C2], g_Q[C2];               // h2 = lrelu(P*k + Q)
__device__ unsigned char      g_k2[(size_t)NB * C2 * HH * WW];// 64MB layer2 popcounts

// ---------------- packed f32x2 FMA (SASS FFMA2: 2 exact fp32 FMAs / issue slot) -----
__device__ __forceinline__ unsigned long long fma2(unsigned long long a,
                                                   unsigned long long b,
                                                   unsigned long long c) {
    unsigned long long d;
    asm("fma.rn.f32x2 %0, %1, %2, %3;" : "=l"(d) : "l"(a), "l"(b), "l"(c));
    return d;
}

// ---------------- pack sign(x) into bitmap; block 0 also packs weights + zeroes stats
__global__ void k_packx(const float* __restrict__ x,
                        const float* __restrict__ w1,
                        const float* __restrict__ w2) {
    int t = threadIdx.x;
    if (blockIdx.x == 0) {
        if (t < C1) {
            unsigned long long b = 0ull;
            #pragma unroll
            for (int j = 0; j < 49; j++)
                if (w1[t * 49 + j] >= 0.f) b |= (1ull << j);
            g_wb1[t] = b;
            g_s1[t] = 0ull;
            g_q1[t] = 0ull;
        }
        if (t < C2) {
            uint32_t w[4];
            #pragma unroll
            for (int q = 0; q < 4; q++) {
                uint32_t b = 0u;
                #pragma unroll
                for (int j = 0; j < 32; j++)
                    if (w2[t * 128 + q * 32 + j] >= 0.f) b |= (1u << j);
                w[q] = b;
            }
            g_wb2[t] = make_uint4(w[0], w[1], w[2], w[3]);
            g_sk[t] = 0ull;
            g_qk[t] = 0ull;
        }
    }
    int idx = blockIdx.x * 256 + t;
    unsigned b = __ballot_sync(0xFFFFFFFFu, x[idx] >= 0.f);
    if ((t & 31) == 0) g_xbits[idx >> 5] = b;
}

// ---------------- 7x7 window of sign bits + validity mask (border-safe) -------------
__device__ __forceinline__ void build_window(int n, int y, int x,
                                             unsigned long long& win,
                                             unsigned long long& msk) {
    const uint32_t* rowbase = g_xbits + (n << 11);
    uint32_t colmask = 0x7Fu;
    if (x < 3)   colmask &= (0x7Fu << (3 - x));
    if (x > 252) colmask &= (0x7Fu >> (x - 252));
    colmask &= 0x7Fu;
    int base = x - 3;
    int wi = (base >= 0) ? (base >> 5) : -1;
    int sh = base & 31;
    win = 0ull; msk = 0ull;
    #pragma unroll
    for (int r = 0; r < 7; r++) {
        int yy = y + r - 3;
        if (yy >= 0 && yy < HH) {
            const uint32_t* rw = rowbase + (yy << 3);
            uint32_t w0 = (wi >= 0) ? rw[wi] : 0u;
            uint32_t w1 = (wi < 7) ? rw[wi + 1] : 0u;
            uint32_t bits = __funnelshift_r(w0, w1, sh) & colmask;
            win |= (unsigned long long)bits << (7 * r);
            msk |= (unsigned long long)colmask << (7 * r);
        }
    }
}

// ---------------- unguarded interior window from shared row bits --------------------
__device__ __forceinline__ unsigned long long win_from_rows(const uint32_t* rb) {
    unsigned long long w = 0ull;
    #pragma unroll
    for (int r = 0; r < 7; r++)
        w |= (unsigned long long)rb[r] << (7 * r);
    return w;
}

// ---------------- pass 1: layer1 conv -> per-channel integer stats ----------------
__global__ void k_conv1_stats() {
    __shared__ unsigned long long s_wb[C1];
    __shared__ int s_sum[C1];
    __shared__ int s_sq[C1];
    int t = threadIdx.x;
    if (t < C1) { s_wb[t] = g_wb1[t]; s_sum[t] = 0; s_sq[t] = 0; }
    __syncthreads();

    int base = blockIdx.x * 2048 + t;
    int n  = base >> 16;
    int r0 = (blockIdx.x * 8) & 255;     // first of 8 rows this block covers
    int x  = t;                          // column (block spans full rows)
    int lane = t & 31;
    int xw = t & 224;                    // warp x-start (multiple of 32)
    bool wint = (xw != 0) && (xw != 224) && (r0 >= 8) && (r0 <= 240);

    if (wint) {
        // ---- interior fast path ----
        const uint32_t* rowbase = g_xbits + (n << 11);
        int bm3 = x - 3;                 // x in [32,223] -> wi in [0,6]
        int wi = bm3 >> 5;
        int sh = bm3 & 31;
        uint32_t rb[14];
        #pragma unroll
        for (int j = 0; j < 14; j++) {
            const uint32_t* rw = rowbase + ((r0 - 3 + j) << 3);
            rb[j] = __funnelshift_r(rw[wi], rw[wi + 1], sh) & 0x7Fu;
        }
        unsigned long long win[8];
        #pragma unroll
        for (int k = 0; k < 8; k++) win[k] = win_from_rows(rb + k);

        #pragma unroll 4
        for (int c = 0; c < C1; c++) {
            unsigned long long wb = s_wb[c];
            int sd = 0, sdd = 0;
            #pragma unroll
            for (int k = 0; k < 8; k++) {
                int d = __popcll(win[k] ^ wb);
                sd += d;
                sdd += d * d;
            }
            int Sd  = __reduce_add_sync(0xFFFFFFFFu, sd);
            int Sdd = __reduce_add_sync(0xFFFFFFFFu, sdd);
            if (lane == 0) {
                // 256 px/warp: sum v = 256*49 - 2*Sd ; sum v^2 = 256*2401 - 196*Sd + 4*Sdd
                atomicAdd(&s_sum[c], 12544 - 2 * Sd);
                atomicAdd(&s_sq[c], 614656 - 196 * Sd + 4 * Sdd);
            }
        }
    } else {
        // ---- border path (exact masks) ----
        unsigned long long win[8], msk[8];
        int inb[8];
        #pragma unroll
        for (int k = 0; k < 8; k++) {
            int p = base + k * 256;
            int rem = p & 65535;
            build_window(n, rem >> 8, rem & 255, win[k], msk[k]);
            inb[k] = __popcll(msk[k]);
        }
        #pragma unroll 4
        for (int c = 0; c < C1; c++) {
            unsigned long long wb = s_wb[c];
            int s = 0, s2 = 0;
            #pragma unroll
            for (int k = 0; k < 8; k++) {
                int d = __popcll((win[k] ^ wb) & msk[k]);
                int v = inb[k] - 2 * d;
                s += v;
                s2 += v * v;
            }
            s  = __reduce_add_sync(0xFFFFFFFFu, s);
            s2 = __reduce_add_sync(0xFFFFFFFFu, s2);
            if (lane == 0) { atomicAdd(&s_sum[c], s); atomicAdd(&s_sq[c], s2); }
        }
    }
    __syncthreads();
    if (t < C1) {
        atomicAdd(&g_s1[t], (unsigned long long)(long long)s_sum[t]);
        atomicAdd(&g_q1[t], (unsigned long long)(long long)s_sq[t]);
    }
}

// ---------------- finalize BN1 -> sign-threshold intervals (v and d domains) --------
__global__ void k_fin1(const float* __restrict__ g1, const float* __restrict__ b1) {
    int c = threadIdx.x;
    if (c >= C1) return;
    double N = (double)NPIX;
    double S1 = (double)(long long)g_s1[c];
    double S2 = (double)g_q1[c];
    double mean = S1 / N;
    double var  = S2 / N - mean * mean;
    float meanf = (float)mean;
    float invf  = g1[c] * rsqrtf((float)var + 1e-5f);
    float beta  = b1[c];
    int lo = 100, hi = -100;
    bool any = false;
    for (int v = -49; v <= 49; v++) {
        float h = ((float)v - meanf) * invf + beta;
        if (h >= 0.f) { if (!any) { lo = v; any = true; } hi = v; }
    }
    int ilo = 100, iwd = 0;                 // d-interval for interior (v = 49-2d)
    if (!any) { g_lo[c] = 100; g_wd[c] = 0; }
    else {
        g_lo[c] = lo;  g_wd[c] = hi - lo;
        int dlo = (49 - hi + 1) >> 1;       // ceil((49-hi)/2)
        int dhi = (49 - lo) >> 1;           // floor((49-lo)/2)
        if (dlo < 0) dlo = 0;
        if (dhi > 49) dhi = 49;
        if (dhi >= dlo) { ilo = dlo; iwd = dhi - dlo; }
    }
    g_ilo[c] = ilo; g_iwd[c] = iwd;
}

// ---------------- pass 3: layer1 signs -> layer2 1x1 binary conv (store k) -----------
__global__ void k_sign_conv2() {
    __shared__ unsigned long long s_wb[C1];
    __shared__ int2 s_vi[C1];          // (lo, wd)  border
    __shared__ int2 s_di[C1];          // (ilo, iwd) interior
    __shared__ uint4 s_w2[C2];
    int t = threadIdx.x;
    if (t < C1) {
        s_wb[t] = g_wb1[t];
        s_vi[t] = make_int2(g_lo[t], g_wd[t]);
        s_di[t] = make_int2(g_ilo[t], g_iwd[t]);
    }
    if (t < C2) s_w2[t] = g_wb2[t];
    __syncthreads();

    int p = blockIdx.x * 256 + t;
    int n = p >> 16;
    int rem = p & 65535;
    int y = rem >> 8;                  // block-uniform (one row per block)
    int x = t;
    int xw = t & 224;
    bool wint = (xw != 0) && (xw != 224) && (y >= 3) && (y <= 252);

    uint32_t sw[4];
    if (wint) {
        // interior: unguarded window, threshold directly on d
        const uint32_t* rowbase = g_xbits + (n << 11);
        int bm3 = x - 3;
        int wi = bm3 >> 5;
        int sh = bm3 & 31;
        unsigned long long win = 0ull;
        #pragma unroll
        for (int r = 0; r < 7; r++) {
            const uint32_t* rw = rowbase + ((y + r - 3) << 3);
            uint32_t bits = __funnelshift_r(rw[wi], rw[wi + 1], sh) & 0x7Fu;
            win |= (unsigned long long)bits << (7 * r);
        }
        #pragma unroll
        for (int w = 0; w < 4; w++) {
            uint32_t bits = 0u;
            #pragma unroll
            for (int j = 0; j < 32; j++) {
                int c = w * 32 + j;
                int d = __popcll(win ^ s_wb[c]);
                int2 di = s_di[c];
                if ((unsigned)(d - di.x) <= (unsigned)di.y) bits |= (1u << j);
            }
            sw[w] = bits;
        }
    } else {
        unsigned long long win, msk;
        build_window(n, y, x, win, msk);
        int inb = __popcll(msk);
        #pragma unroll
        for (int w = 0; w < 4; w++) {
            uint32_t bits = 0u;
            #pragma unroll
            for (int j = 0; j < 32; j++) {
                int c = w * 32 + j;
                int dis = __popcll((win ^ s_wb[c]) & msk);
                int v = inb - 2 * dis;
                int2 vi = s_vi[c];
                if ((unsigned)(v - vi.x) <= (unsigned)vi.y) bits |= (1u << j);
            }
            sw[w] = bits;
        }
    }

    unsigned char* outb = g_k2 + ((size_t)n << 22) + rem;
    #pragma unroll 8
    for (int oc = 0; oc < C2; oc++) {
        uint4 wb = s_w2[oc];
        int k = __popc(sw[0] ^ wb.x) + __popc(sw[1] ^ wb.y) +
                __popc(sw[2] ^ wb.z) + __popc(sw[3] ^ wb.w);
        outb[(size_t)oc << 16] = (unsigned char)k;
    }
}

// ---------------- stats for BN2 from k bytes (dp4a) ----------------
__global__ void k_stats2() {
    int b = blockIdx.x;           // b = n*64 + c
    int c = b & 63;
    int t = threadIdx.x;
    const uint4* ptr = (const uint4*)(g_k2 + ((size_t)b << 16));
    unsigned s = 0u, s2 = 0u;
    #pragma unroll
    for (int i = 0; i < 16; i++) {
        uint4 v = ptr[t + i * 256];
        s  = __dp4a(v.x, 0x01010101u, s);  s2 = __dp4a(v.x, v.x, s2);
        s  = __dp4a(v.y, 0x01010101u, s);  s2 = __dp4a(v.y, v.y, s2);
        s  = __dp4a(v.z, 0x01010101u, s);  s2 = __dp4a(v.z, v.z, s2);
        s  = __dp4a(v.w, 0x01010101u, s);  s2 = __dp4a(v.w, v.w, s2);
    }
    s  = __reduce_add_sync(0xFFFFFFFFu, s);
    s2 = __reduce_add_sync(0xFFFFFFFFu, s2);
    __shared__ unsigned sh_s, sh_s2;
    if (t == 0) { sh_s = 0u; sh_s2 = 0u; }
    __syncthreads();
    if ((t & 31) == 0) { atomicAdd(&sh_s, s); atomicAdd(&sh_s2, s2); }
    __syncthreads();
    if (t == 0) {
        atomicAdd(&g_sk[c], (unsigned long long)sh_s);
        atomicAdd(&g_qk[c], (unsigned long long)sh_s2);
    }
}

// ---------------- finalize BN2 -> affine h2(k) = lrelu(P*k + Q) ----------------
__global__ void k_fin2(const float* __restrict__ g2, const float* __restrict__ b2) {
    int c = threadIdx.x;
    if (c >= C2) return;
    double N = (double)NPIX;
    double mk = (double)(long long)g_sk[c] / N;
    double qk = (double)g_qk[c] / N;
    double vark = qk - mk * mk;
    float meanv = (float)(128.0 - 2.0 * mk);
    float varv  = (float)(4.0 * vark);
    float inv   = g2[c] * rsqrtf(varv + 1e-5f);
    g_P[c] = -2.f * inv;
    g_Q[c] = (128.f - meanv) * inv + b2[c];
}

// ---------------- layer 3: fp32 5x5 conv, 64 ch -> 1 ch, f32x2-packed ----------------
// Channel-PAIR interleaved smem: ht2[pair][row][2*col + (c&1)] so every aligned
// 8/16-byte load yields a natural (c_even, c_odd) register pair for fma.rn.f32x2.
// Thread tile: 4 rows x 2 cols -> lane stride 16B -> each 8-lane LDS.128 phase
// covers one contiguous 128B line (conflict-free). 100 FMA2 per thread per pair
// (= 200 fp32 FMAs) with 25 weight-pairs register-resident.
__global__ void __launch_bounds__(128, 4) k_conv3(const float* __restrict__ w3,
                                                  float* __restrict__ out) {
    __shared__ float ht2[4][36][72];    // 41,472 B  [pair][row][2*col+sub]
    __shared__ float w3p[32][25][2];    //  6,400 B  weight pairs
    __shared__ float Ps[C2], Qs[C2];    //    512 B
    int t  = threadIdx.x;               // 0..127
    int tx = t & 15;                    // 0..15 : cols 2*tx
    int ty = t >> 4;                    // 0..7  : rows 4*ty
    for (int i = t; i < 1600; i += 128) {
        int pp = i / 50;
        int rm = i % 50;
        int tap = rm >> 1;
        int sub = rm & 1;
        w3p[pp][tap][sub] = w3[(2 * pp + sub) * 25 + tap];
    }
    if (t < C2) { Ps[t] = g_P[t]; Qs[t] = g_Q[t]; }

    int n = blockIdx.z;
    int X0 = blockIdx.x * 32;
    int Y0 = blockIdx.y * 32;
    const unsigned char* kbase = g_k2 + ((size_t)n << 22);

    unsigned long long acc[4][2];
    #pragma unroll
    for (int ry = 0; ry < 4; ry++) { acc[ry][0] = 0ull; acc[ry][1] = 0ull; }

    for (int g = 0; g < 8; g++) {
        int c0 = g * 8;
        __syncthreads();
        // fill 36x36 halo tile for 8 channels (4 pairs), k -> lrelu(P*k+Q)
        for (int i = t; i < 1296; i += 128) {
            int yy = i / 36;
            int xx = i - yy * 36;
            int gy = Y0 - 2 + yy;
            int gx = X0 - 2 + xx;
            bool ok = ((unsigned)gy < 256u) && ((unsigned)gx < 256u);
            int off = gy * 256 + gx;
            #pragma unroll
            for (int pr = 0; pr < 4; pr++) {
                float v0 = 0.f, v1 = 0.f;
                if (ok) {
                    int ca = c0 + 2 * pr;
                    float k0 = (float)kbase[((size_t)ca << 16) + off];
                    float k1 = (float)kbase[((size_t)(ca + 1) << 16) + off];
                    float h0 = fmaf(Ps[ca], k0, Qs[ca]);
                    float h1 = fmaf(Ps[ca + 1], k1, Qs[ca + 1]);
                    v0 = fmaxf(h0, 0.5f * h0);
                    v1 = fmaxf(h1, 0.5f * h1);
                }
                *(float2*)&ht2[pr][yy][2 * xx] = make_float2(v0, v1);
            }
        }
        __syncthreads();

        for (int pr = 0; pr < 4; pr++) {
            // preload 25 weight pairs into registers (constant indices after unroll)
            unsigned long long wp[25];
            const unsigned long long* wb =
                (const unsigned long long*)&w3p[(c0 >> 1) + pr][0][0];
            #pragma unroll
            for (int tap = 0; tap < 25; tap++) wp[tap] = wb[tap];

            #pragma unroll
            for (int rr = 0; rr < 8; rr++) {
                const float* rowp = &ht2[pr][ty * 4 + rr][4 * tx];
                ulonglong2 q0 = *(const ulonglong2*)(rowp);
                ulonglong2 q1 = *(const ulonglong2*)(rowp + 4);
                ulonglong2 q2 = *(const ulonglong2*)(rowp + 8);
                unsigned long long P0 = q0.x, P1 = q0.y, P2 = q1.x,
                                   P3 = q1.y, P4 = q2.x, P5 = q2.y;
                #pragma unroll
                for (int ky = 0; ky < 5; ky++) {
                    int ry = rr - ky;
                    if (ry >= 0 && ry < 4) {
                        unsigned long long w0 = wp[ky * 5 + 0];
                        unsigned long long w1 = wp[ky * 5 + 1];
                        unsigned long long w2 = wp[ky * 5 + 2];
                        unsigned long long w3v = wp[ky * 5 + 3];
                        unsigned long long w4 = wp[ky * 5 + 4];
                        acc[ry][0] = fma2(P0, w0, acc[ry][0]);
                        acc[ry][1] = fma2(P1, w0, acc[ry][1]);
                        acc[ry][0] = fma2(P1, w1, acc[ry][0]);
                        acc[ry][1] = fma2(P2, w1, acc[ry][1]);
                        acc[ry][0] = fma2(P2, w2, acc[ry][0]);
                        acc[ry][1] = fma2(P3, w2, acc[ry][1]);
                        acc[ry][0] = fma2(P3, w3v, acc[ry][0]);
                        acc[ry][1] = fma2(P4, w3v, acc[ry][1]);
                        acc[ry][0] = fma2(P4, w4, acc[ry][0]);
                        acc[ry][1] = fma2(P5, w4, acc[ry][1]);
                    }
                }
            }
        }
    }

    #pragma unroll
    for (int ry = 0; ry < 4; ry++) {
        int yo = Y0 + ty * 4 + ry;
        float r0 = __uint_as_float((unsigned)acc[ry][0]) +
                   __uint_as_float((unsigned)(acc[ry][0] >> 32));
        float r1 = __uint_as_float((unsigned)acc[ry][1]) +
                   __uint_as_float((unsigned)(acc[ry][1] >> 32));
        *(float2*)&out[(n << 16) + yo * 256 + X0 + 2 * tx] = make_float2(r0, r1);
    }
}

// ---------------- launch ----------------
extern "C" void kernel_launch(void* const* d_in, const int* in_sizes, int n_in,
                              void* d_out, int out_size) {
    const float* x  = (const float*)d_in[0];
    const float* w1 = (const float*)d_in[1];
    const float* g1 = (const float*)d_in[2];
    const float* b1 = (const float*)d_in[3];
    const float* w2 = (const float*)d_in[4];
    const float* g2 = (const float*)d_in[5];
    const float* b2 = (const float*)d_in[6];
    const float* w3 = (const float*)d_in[7];
    float* out = (float*)d_out;

    k_packx<<<NPIX / 256, 256>>>(x, w1, w2);
    k_conv1_stats<<<NPIX / 2048, 256>>>();
    k_fin1<<<1, 128>>>(g1, b1);
    k_sign_conv2<<<NPIX / 256, 256>>>();
    k_stats2<<<NB * C2, 256>>>();
    k_fin2<<<1, 64>>>(g2, b2);
    k_conv3<<<dim3(8, 8, NB), dim3(128)>>>(w3, out);
    (void)in_sizes; (void)n_in; (void)out_size;
}

// round 9
// speedup vs baseline: 1.7611x; 1.0464x over previous
#include <cuda_runtime.h>
#include <cstdint>
#include <cstddef>

#define NB 16
#define HH 256
#define WW 256
#define NPIX (NB * HH * WW)        // 1,048,576 pixels (per-channel BN count)
#define C1 128
#define C2 64

// ---------------- static device scratch (no allocations allowed) ----------------
__device__ uint32_t           g_xbits[NB * HH * (WW / 32)];   // packed sign(x), 128KB
__device__ unsigned long long g_wb1[C1];                      // 49-bit weight signs, layer1
__device__ uint4              g_wb2[C2];                      // 128-bit weight signs, layer2
__device__ unsigned long long g_s1[C1];                       // sum v1 (2's complement)
__device__ unsigned long long g_q1[C1];                       // sum v1^2
__device__ int                g_lo[C1];                       // v-interval lo (border path)
__device__ int                g_wd[C1];                       // v-interval width
__device__ int                g_ilo[C1];                      // d-interval lo (interior path)
__device__ int                g_iwd[C1];                      // d-interval width
__device__ unsigned long long g_sk[C2];                       // sum k
__device__ unsigned long long g_qk[C2];                       // sum k^2
__device__ float              g_P[C2], g_Q[C2];               // h2 = lrelu(P*k + Q)
__device__ uint32_t           g_d1[(size_t)32 * NPIX];        // 128MB: d packed 4ch/word, [cg][px]
__device__ unsigned char      g_k2[(size_t)NB * C2 * HH * WW];// 64MB layer2 popcounts

// ---------------- packed f32x2 FMA (SASS FFMA2: 2 exact fp32 FMAs / issue slot) -----
__device__ __forceinline__ unsigned long long fma2(unsigned long long a,
                                                   unsigned long long b,
                                                   unsigned long long c) {
    unsigned long long d;
    asm("fma.rn.f32x2 %0, %1, %2, %3;" : "=l"(d) : "l"(a), "l"(b), "l"(c));
    return d;
}

// ---------------- pack sign(x) into bitmap; block 0 also packs weights + zeroes stats
__global__ void k_packx(const float* __restrict__ x,
                        const float* __restrict__ w1,
                        const float* __restrict__ w2) {
    int t = threadIdx.x;
    if (blockIdx.x == 0) {
        if (t < C1) {
            unsigned long long b = 0ull;
            #pragma unroll
            for (int j = 0; j < 49; j++)
                if (w1[t * 49 + j] >= 0.f) b |= (1ull << j);
            g_wb1[t] = b;
            g_s1[t] = 0ull;
            g_q1[t] = 0ull;
        }
        if (t < C2) {
            uint32_t w[4];
            #pragma unroll
            for (int q = 0; q < 4; q++) {
                uint32_t b = 0u;
                #pragma unroll
                for (int j = 0; j < 32; j++)
                    if (w2[t * 128 + q * 32 + j] >= 0.f) b |= (1u << j);
                w[q] = b;
            }
            g_wb2[t] = make_uint4(w[0], w[1], w[2], w[3]);
            g_sk[t] = 0ull;
            g_qk[t] = 0ull;
        }
    }
    int idx = blockIdx.x * 256 + t;
    unsigned b = __ballot_sync(0xFFFFFFFFu, x[idx] >= 0.f);
    if ((t & 31) == 0) g_xbits[idx >> 5] = b;
}

// ---------------- 7x7 window of sign bits + validity mask (border-safe) -------------
__device__ __forceinline__ void build_window(int n, int y, int x,
                                             unsigned long long& win,
                                             unsigned long long& msk) {
    const uint32_t* rowbase = g_xbits + (n << 11);
    uint32_t colmask = 0x7Fu;
    if (x < 3)   colmask &= (0x7Fu << (3 - x));
    if (x > 252) colmask &= (0x7Fu >> (x - 252));
    colmask &= 0x7Fu;
    int base = x - 3;
    int wi = (base >= 0) ? (base >> 5) : -1;
    int sh = base & 31;
    win = 0ull; msk = 0ull;
    #pragma unroll
    for (int r = 0; r < 7; r++) {
        int yy = y + r - 3;
        if (yy >= 0 && yy < HH) {
            const uint32_t* rw = rowbase + (yy << 3);
            uint32_t w0 = (wi >= 0) ? rw[wi] : 0u;
            uint32_t w1 = (wi < 7) ? rw[wi + 1] : 0u;
            uint32_t bits = __funnelshift_r(w0, w1, sh) & colmask;
            win |= (unsigned long long)bits << (7 * r);
            msk |= (unsigned long long)colmask << (7 * r);
        }
    }
}

// ---------------- unguarded interior window from shared row bits --------------------
__device__ __forceinline__ unsigned long long win_from_rows(const uint32_t* rb) {
    unsigned long long w = 0ull;
    #pragma unroll
    for (int r = 0; r < 7; r++)
        w |= (unsigned long long)rb[r] << (7 * r);
    return w;
}

// ---------------- pass 1: layer1 conv -> per-channel integer stats + packed d store --
// 8 pixels per thread. Channel-groups of 4: per pixel, d for 4 channels are packed
// into one uint32 and stored to g_d1[cg][pixel] (coalesced STG.32). Stats math is
// unchanged (exact integers). Border warps store masked-d: those bytes equal the
// true unmasked d exactly on all pixels the pass-2 interior path will read.
__global__ void k_conv1_stats() {
    __shared__ unsigned long long s_wb[C1];
    __shared__ int s_sum[C1];
    __shared__ int s_sq[C1];
    int t = threadIdx.x;
    if (t < C1) { s_wb[t] = g_wb1[t]; s_sum[t] = 0; s_sq[t] = 0; }
    __syncthreads();

    int base = blockIdx.x * 2048 + t;
    int n  = base >> 16;
    int r0 = (blockIdx.x * 8) & 255;     // first of 8 rows this block covers
    int x  = t;                          // column (block spans full rows)
    int lane = t & 31;
    int xw = t & 224;                    // warp x-start (multiple of 32)
    bool wint = (xw != 0) && (xw != 224) && (r0 >= 8) && (r0 <= 240);

    if (wint) {
        // ---- interior fast path: unmasked windows ----
        const uint32_t* rowbase = g_xbits + (n << 11);
        int bm3 = x - 3;
        int wi = bm3 >> 5;
        int sh = bm3 & 31;
        uint32_t rb[14];
        #pragma unroll
        for (int j = 0; j < 14; j++) {
            const uint32_t* rw = rowbase + ((r0 - 3 + j) << 3);
            rb[j] = __funnelshift_r(rw[wi], rw[wi + 1], sh) & 0x7Fu;
        }
        unsigned long long win[8];
        #pragma unroll
        for (int k = 0; k < 8; k++) win[k] = win_from_rows(rb + k);

        #pragma unroll 2
        for (int cg = 0; cg < 32; cg++) {
            unsigned long long wb0 = s_wb[4 * cg + 0];
            unsigned long long wb1 = s_wb[4 * cg + 1];
            unsigned long long wb2 = s_wb[4 * cg + 2];
            unsigned long long wb3 = s_wb[4 * cg + 3];
            int sd0 = 0, sd1 = 0, sd2 = 0, sd3 = 0;
            int q0 = 0, q1 = 0, q2 = 0, q3 = 0;
            #pragma unroll
            for (int k = 0; k < 8; k++) {
                int d0 = __popcll(win[k] ^ wb0);
                int d1 = __popcll(win[k] ^ wb1);
                int d2 = __popcll(win[k] ^ wb2);
                int d3 = __popcll(win[k] ^ wb3);
                sd0 += d0; q0 += d0 * d0;
                sd1 += d1; q1 += d1 * d1;
                sd2 += d2; q2 += d2 * d2;
                sd3 += d3; q3 += d3 * d3;
                g_d1[((size_t)cg << 20) + base + k * 256] =
                    (unsigned)d0 | ((unsigned)d1 << 8) |
                    ((unsigned)d2 << 16) | ((unsigned)d3 << 24);
            }
            #pragma unroll
            for (int j = 0; j < 4; j++) {
                int sd = (j == 0) ? sd0 : (j == 1) ? sd1 : (j == 2) ? sd2 : sd3;
                int qq = (j == 0) ? q0  : (j == 1) ? q1  : (j == 2) ? q2  : q3;
                int Sd  = __reduce_add_sync(0xFFFFFFFFu, sd);
                int Sdd = __reduce_add_sync(0xFFFFFFFFu, qq);
                if (lane == 0) {
                    // 256 px/warp: sum v = 256*49 - 2*Sd ; sum v^2 = 256*2401 - 196*Sd + 4*Sdd
                    atomicAdd(&s_sum[4 * cg + j], 12544 - 2 * Sd);
                    atomicAdd(&s_sq[4 * cg + j], 614656 - 196 * Sd + 4 * Sdd);
                }
            }
        }
    } else {
        // ---- border path (exact masks) ----
        unsigned long long win[8], msk[8];
        int inb[8];
        #pragma unroll
        for (int k = 0; k < 8; k++) {
            int p = base + k * 256;
            int rem = p & 65535;
            build_window(n, rem >> 8, rem & 255, win[k], msk[k]);
            inb[k] = __popcll(msk[k]);
        }
        #pragma unroll 2
        for (int cg = 0; cg < 32; cg++) {
            unsigned long long wb0 = s_wb[4 * cg + 0];
            unsigned long long wb1 = s_wb[4 * cg + 1];
            unsigned long long wb2 = s_wb[4 * cg + 2];
            unsigned long long wb3 = s_wb[4 * cg + 3];
            int s0 = 0, s1 = 0, s2 = 0, s3 = 0;
            int q0 = 0, q1 = 0, q2 = 0, q3 = 0;
            #pragma unroll
            for (int k = 0; k < 8; k++) {
                int d0 = __popcll((win[k] ^ wb0) & msk[k]);
                int d1 = __popcll((win[k] ^ wb1) & msk[k]);
                int d2 = __popcll((win[k] ^ wb2) & msk[k]);
                int d3 = __popcll((win[k] ^ wb3) & msk[k]);
                g_d1[((size_t)cg << 20) + base + k * 256] =
                    (unsigned)d0 | ((unsigned)d1 << 8) |
                    ((unsigned)d2 << 16) | ((unsigned)d3 << 24);
                int v0 = inb[k] - 2 * d0;
                int v1 = inb[k] - 2 * d1;
                int v2 = inb[k] - 2 * d2;
                int v3 = inb[k] - 2 * d3;
                s0 += v0; q0 += v0 * v0;
                s1 += v1; q1 += v1 * v1;
                s2 += v2; q2 += v2 * v2;
                s3 += v3; q3 += v3 * v3;
            }
            #pragma unroll
            for (int j = 0; j < 4; j++) {
                int ss = (j == 0) ? s0 : (j == 1) ? s1 : (j == 2) ? s2 : s3;
                int qq = (j == 0) ? q0 : (j == 1) ? q1 : (j == 2) ? q2 : q3;
                int S  = __reduce_add_sync(0xFFFFFFFFu, ss);
                int Q  = __reduce_add_sync(0xFFFFFFFFu, qq);
                if (lane == 0) {
                    atomicAdd(&s_sum[4 * cg + j], S);
                    atomicAdd(&s_sq[4 * cg + j], Q);
                }
            }
        }
    }
    __syncthreads();
    if (t < C1) {
        atomicAdd(&g_s1[t], (unsigned long long)(long long)s_sum[t]);
        atomicAdd(&g_q1[t], (unsigned long long)(long long)s_sq[t]);
    }
}

// ---------------- finalize BN1 -> sign-threshold intervals (v and d domains) --------
__global__ void k_fin1(const float* __restrict__ g1, const float* __restrict__ b1) {
    int c = threadIdx.x;
    if (c >= C1) return;
    double N = (double)NPIX;
    double S1 = (double)(long long)g_s1[c];
    double S2 = (double)g_q1[c];
    double mean = S1 / N;
    double var  = S2 / N - mean * mean;
    float meanf = (float)mean;
    float invf  = g1[c] * rsqrtf((float)var + 1e-5f);
    float beta  = b1[c];
    int lo = 100, hi = -100;
    bool any = false;
    for (int v = -49; v <= 49; v++) {
        float h = ((float)v - meanf) * invf + beta;
        if (h >= 0.f) { if (!any) { lo = v; any = true; } hi = v; }
    }
    int ilo = 100, iwd = 0;                 // d-interval for interior (v = 49-2d)
    if (!any) { g_lo[c] = 100; g_wd[c] = 0; }
    else {
        g_lo[c] = lo;  g_wd[c] = hi - lo;
        int dlo = (49 - hi + 1) >> 1;       // ceil((49-hi)/2)
        int dhi = (49 - lo) >> 1;           // floor((49-lo)/2)
        if (dlo < 0) dlo = 0;
        if (dhi > 49) dhi = 49;
        if (dhi >= dlo) { ilo = dlo; iwd = dhi - dlo; }
    }
    g_ilo[c] = ilo; g_iwd[c] = iwd;
}

// ---------------- pass 3: stored d -> SWAR threshold -> layer2 1x1 binary conv ------
// Interior: load packed d words and test 4 channels at once with byte-SWAR range
// checks (no borrows: d<=49, bounds<=100, bias 0x80), then gather the 4 predicate
// bits with one carry-free IMAD spread. Border warps recompute exactly as before.
__global__ void k_sign_conv2() {
    __shared__ unsigned long long s_wb[C1];
    __shared__ int2 s_vi[C1];          // (lo, wd)  border, v-domain
    __shared__ unsigned s_LO[32];      // packed lo bytes (4 ch/word)
    __shared__ unsigned s_HIO[32];     // packed (hi|0x80) bytes
    __shared__ uint4 s_w2[C2];
    int t = threadIdx.x;
    if (t < C1) {
        s_wb[t] = g_wb1[t];
        s_vi[t] = make_int2(g_lo[t], g_wd[t]);
    }
    if (t < 32) {
        unsigned lo = 0, hio = 0;
        #pragma unroll
        for (int j = 0; j < 4; j++) {
            int c = 4 * t + j;
            lo  |= (unsigned)g_ilo[c] << (8 * j);
            hio |= (unsigned)((g_ilo[c] + g_iwd[c]) | 0x80) << (8 * j);
        }
        s_LO[t] = lo; s_HIO[t] = hio;
    }
    if (t < C2) s_w2[t] = g_wb2[t];
    __syncthreads();

    int p = blockIdx.x * 256 + t;
    int n = p >> 16;
    int rem = p & 65535;
    int y = rem >> 8;                  // block-uniform (one row per block)
    int xw = t & 224;
    bool wint = (xw != 0) && (xw != 224) && (y >= 3) && (y <= 252);

    uint32_t sw[4];
    if (wint) {
        unsigned m0 = 0, m1 = 0, m2 = 0, m3 = 0;
        #pragma unroll
        for (int cg = 0; cg < 32; cg++) {
            unsigned D = g_d1[((size_t)cg << 20) + p];
            unsigned ge = (D | 0x80808080u) - s_LO[cg];
            unsigned le = s_HIO[cg] - D;
            unsigned both = ge & le & 0x80808080u;
            // bits at 7,15,23,31 -> >>7 puts them at 0,8,16,24; multiply gathers
            // them carry-free into bits 24..27 (all contribution bits distinct)
            unsigned nib = (((both >> 7) * 0x01020408u) >> 24) & 0xFu;
            unsigned sh = 4 * (cg & 7);
            if ((cg >> 3) == 0) m0 |= nib << sh;
            else if ((cg >> 3) == 1) m1 |= nib << sh;
            else if ((cg >> 3) == 2) m2 |= nib << sh;
            else m3 |= nib << sh;
        }
        sw[0] = m0; sw[1] = m1; sw[2] = m2; sw[3] = m3;
    } else {
        unsigned long long win, msk;
        build_window(n, y, t, win, msk);
        int inb = __popcll(msk);
        #pragma unroll
        for (int w = 0; w < 4; w++) {
            uint32_t bits = 0u;
            #pragma unroll
            for (int j = 0; j < 32; j++) {
                int c = w * 32 + j;
                int dis = __popcll((win ^ s_wb[c]) & msk);
                int v = inb - 2 * dis;
                int2 vi = s_vi[c];
                if ((unsigned)(v - vi.x) <= (unsigned)vi.y) bits |= (1u << j);
            }
            sw[w] = bits;
        }
    }

    unsigned char* outb = g_k2 + ((size_t)n << 22) + rem;
    #pragma unroll 8
    for (int oc = 0; oc < C2; oc++) {
        uint4 wb = s_w2[oc];
        int k = __popc(sw[0] ^ wb.x) + __popc(sw[1] ^ wb.y) +
                __popc(sw[2] ^ wb.z) + __popc(sw[3] ^ wb.w);
        outb[(size_t)oc << 16] = (unsigned char)k;
    }
}

// ---------------- stats for BN2 from k bytes (dp4a) ----------------
__global__ void k_stats2() {
    int b = blockIdx.x;           // b = n*64 + c
    int c = b & 63;
    int t = threadIdx.x;
    const uint4* ptr = (const uint4*)(g_k2 + ((size_t)b << 16));
    unsigned s = 0u, s2 = 0u;
    #pragma unroll
    for (int i = 0; i < 16; i++) {
        uint4 v = ptr[t + i * 256];
        s  = __dp4a(v.x, 0x01010101u, s);  s2 = __dp4a(v.x, v.x, s2);
        s  = __dp4a(v.y, 0x01010101u, s);  s2 = __dp4a(v.y, v.y, s2);
        s  = __dp4a(v.z, 0x01010101u, s);  s2 = __dp4a(v.z, v.z, s2);
        s  = __dp4a(v.w, 0x01010101u, s);  s2 = __dp4a(v.w, v.w, s2);
    }
    s  = __reduce_add_sync(0xFFFFFFFFu, s);
    s2 = __reduce_add_sync(0xFFFFFFFFu, s2);
    __shared__ unsigned sh_s, sh_s2;
    if (t == 0) { sh_s = 0u; sh_s2 = 0u; }
    __syncthreads();
    if ((t & 31) == 0) { atomicAdd(&sh_s, s); atomicAdd(&sh_s2, s2); }
    __syncthreads();
    if (t == 0) {
        atomicAdd(&g_sk[c], (unsigned long long)sh_s);
        atomicAdd(&g_qk[c], (unsigned long long)sh_s2);
    }
}

// ---------------- finalize BN2 -> affine h2(k) = lrelu(P*k + Q) ----------------
__global__ void k_fin2(const float* __restrict__ g2, const float* __restrict__ b2) {
    int c = threadIdx.x;
    if (c >= C2) return;
    double N = (double)NPIX;
    double mk = (double)(long long)g_sk[c] / N;
    double qk = (double)g_qk[c] / N;
    double vark = qk - mk * mk;
    float meanv = (float)(128.0 - 2.0 * mk);
    float varv  = (float)(4.0 * vark);
    float inv   = g2[c] * rsqrtf(varv + 1e-5f);
    g_P[c] = -2.f * inv;
    g_Q[c] = (128.f - meanv) * inv + b2[c];
}

// ---------------- layer 3: fp32 5x5 conv, 64 ch -> 1 ch, f32x2-packed ----------------
__global__ void __launch_bounds__(128, 4) k_conv3(const float* __restrict__ w3,
                                                  float* __restrict__ out) {
    __shared__ float ht2[4][36][72];    // 41,472 B  [pair][row][2*col+sub]
    __shared__ float w3p[32][25][2];    //  6,400 B  weight pairs
    __shared__ float Ps[C2], Qs[C2];    //    512 B
    int t  = threadIdx.x;               // 0..127
    int tx = t & 15;                    // 0..15 : cols 2*tx
    int ty = t >> 4;                    // 0..7  : rows 4*ty
    for (int i = t; i < 1600; i += 128) {
        int pp = i / 50;
        int rm = i % 50;
        int tap = rm >> 1;
        int sub = rm & 1;
        w3p[pp][tap][sub] = w3[(2 * pp + sub) * 25 + tap];
    }
    if (t < C2) { Ps[t] = g_P[t]; Qs[t] = g_Q[t]; }

    int n = blockIdx.z;
    int X0 = blockIdx.x * 32;
    int Y0 = blockIdx.y * 32;
    const unsigned char* kbase = g_k2 + ((size_t)n << 22);

    unsigned long long acc[4][2];
    #pragma unroll
    for (int ry = 0; ry < 4; ry++) { acc[ry][0] = 0ull; acc[ry][1] = 0ull; }

    for (int g = 0; g < 8; g++) {
        int c0 = g * 8;
        __syncthreads();
        for (int i = t; i < 1296; i += 128) {
            int yy = i / 36;
            int xx = i - yy * 36;
            int gy = Y0 - 2 + yy;
            int gx = X0 - 2 + xx;
            bool ok = ((unsigned)gy < 256u) && ((unsigned)gx < 256u);
            int off = gy * 256 + gx;
            #pragma unroll
            for (int pr = 0; pr < 4; pr++) {
                float v0 = 0.f, v1 = 0.f;
                if (ok) {
                    int ca = c0 + 2 * pr;
                    float k0 = (float)kbase[((size_t)ca << 16) + off];
                    float k1 = (float)kbase[((size_t)(ca + 1) << 16) + off];
                    float h0 = fmaf(Ps[ca], k0, Qs[ca]);
                    float h1 = fmaf(Ps[ca + 1], k1, Qs[ca + 1]);
                    v0 = fmaxf(h0, 0.5f * h0);
                    v1 = fmaxf(h1, 0.5f * h1);
                }
                *(float2*)&ht2[pr][yy][2 * xx] = make_float2(v0, v1);
            }
        }
        __syncthreads();

        for (int pr = 0; pr < 4; pr++) {
            unsigned long long wp[25];
            const unsigned long long* wb =
                (const unsigned long long*)&w3p[(c0 >> 1) + pr][0][0];
            #pragma unroll
            for (int tap = 0; tap < 25; tap++) wp[tap] = wb[tap];

            #pragma unroll
            for (int rr = 0; rr < 8; rr++) {
                const float* rowp = &ht2[pr][ty * 4 + rr][4 * tx];
                ulonglong2 q0 = *(const ulonglong2*)(rowp);
                ulonglong2 q1 = *(const ulonglong2*)(rowp + 4);
                ulonglong2 q2 = *(const ulonglong2*)(rowp + 8);
                unsigned long long P0 = q0.x, P1 = q0.y, P2 = q1.x,
                                   P3 = q1.y, P4 = q2.x, P5 = q2.y;
                #pragma unroll
                for (int ky = 0; ky < 5; ky++) {
                    int ry = rr - ky;
                    if (ry >= 0 && ry < 4) {
                        unsigned long long w0 = wp[ky * 5 + 0];
                        unsigned long long w1 = wp[ky * 5 + 1];
                        unsigned long long w2 = wp[ky * 5 + 2];
                        unsigned long long w3v = wp[ky * 5 + 3];
                        unsigned long long w4 = wp[ky * 5 + 4];
                        acc[ry][0] = fma2(P0, w0, acc[ry][0]);
                        acc[ry][1] = fma2(P1, w0, acc[ry][1]);
                        acc[ry][0] = fma2(P1, w1, acc[ry][0]);
                        acc[ry][1] = fma2(P2, w1, acc[ry][1]);
                        acc[ry][0] = fma2(P2, w2, acc[ry][0]);
                        acc[ry][1] = fma2(P3, w2, acc[ry][1]);
                        acc[ry][0] = fma2(P3, w3v, acc[ry][0]);
                        acc[ry][1] = fma2(P4, w3v, acc[ry][1]);
                        acc[ry][0] = fma2(P4, w4, acc[ry][0]);
                        acc[ry][1] = fma2(P5, w4, acc[ry][1]);
                    }
                }
            }
        }
    }

    #pragma unroll
    for (int ry = 0; ry < 4; ry++) {
        int yo = Y0 + ty * 4 + ry;
        float r0 = __uint_as_float((unsigned)acc[ry][0]) +
                   __uint_as_float((unsigned)(acc[ry][0] >> 32));
        float r1 = __uint_as_float((unsigned)acc[ry][1]) +
                   __uint_as_float((unsigned)(acc[ry][1] >> 32));
        *(float2*)&out[(n << 16) + yo * 256 + X0 + 2 * tx] = make_float2(r0, r1);
    }
}

// ---------------- launch ----------------
extern "C" void kernel_launch(void* const* d_in, const int* in_sizes, int n_in,
                              void* d_out, int out_size) {
    const float* x  = (const float*)d_in[0];
    const float* w1 = (const float*)d_in[1];
    const float* g1 = (const float*)d_in[2];
    const float* b1 = (const float*)d_in[3];
    const float* w2 = (const float*)d_in[4];
    const float* g2 = (const float*)d_in[5];
    const float* b2 = (const float*)d_in[6];
    const float* w3 = (const float*)d_in[7];
    float* out = (float*)d_out;

    k_packx<<<NPIX / 256, 256>>>(x, w1, w2);
    k_conv1_stats<<<NPIX / 2048, 256>>>();
    k_fin1<<<1, 128>>>(g1, b1);
    k_sign_conv2<<<NPIX / 256, 256>>>();
    k_stats2<<<NB * C2, 256>>>();
    k_fin2<<<1, 64>>>(g2, b2);
    k_conv3<<<dim3(8, 8, NB), dim3(128)>>>(w3, out);
    (void)in_sizes; (void)n_in; (void)out_size;
}